// round 6
// baseline (speedup 1.0000x reference)
#include <cuda_runtime.h>
#include <cuda_bf16.h>
#include <math.h>

#define DIMC 256
#define SNB  16
#define PHC  128
#define QKVC 768
#define NMAX 32768

// ---------------- static scratch (no allocation allowed) ----------------
__device__ float g_qkv[(size_t)NMAX * QKVC];   // q|k|v per row, 96 MB
__device__ float g_attn[(size_t)NMAX * DIMC];  // 32 MB
__device__ float g_slope[129 * DIMC];
__device__ float g_inter[129 * DIMC];
__device__ float g_bp[130];
__device__ int   g_mask_mode;                  // 0=int32, 1=uint8, 2=float32

// ---------------- mask dtype detection ----------------
__global__ void detect_mask_kernel(const unsigned* __restrict__ m, int nwords) {
    __shared__ int sh_other, sh_float;
    if (threadIdx.x == 0) { sh_other = 0; sh_float = 0; }
    __syncthreads();
    int other = 0, flt = 0;
    for (int i = threadIdx.x; i < nwords; i += blockDim.x) {
        unsigned v = m[i];
        if (v == 0x3f800000u) flt = 1;
        else if (v > 1u) other = 1;
    }
    if (other) sh_other = 1;   // benign race, same value
    if (flt)   sh_float = 1;
    __syncthreads();
    if (threadIdx.x == 0)
        g_mask_mode = sh_other ? 1 : (sh_float ? 2 : 0);
}

// ---------------- piecewise-linear MLP table ----------------
// breakpoints of relu(Wp1[j]*rel + bp1[j]) as a function of scalar rel >= 0
__global__ void build_bp_kernel(const float* __restrict__ Wp1,
                                const float* __restrict__ bp1) {
    __shared__ float t[PHC];
    int j = threadIdx.x;
    float a = Wp1[j], b = bp1[j];
    float INF = __int_as_float(0x7f800000);
    float tj;
    if (a != 0.f) {
        tj = -b / a;
        if (!(tj > 0.f)) tj = 0.f;          // nonpositive or NaN -> 0 (inactive boundary)
        if (isinf(tj)) tj = INF;
    } else {
        tj = INF;                            // constant neuron: no breakpoint
    }
    t[j] = tj;
    __syncthreads();
    // rank sort (stable with index tiebreak)
    int rank = 0;
    for (int i = 0; i < PHC; i++) {
        float ti = t[i];
        rank += (ti < tj) || (ti == tj && i < j);
    }
    g_bp[rank + 1] = tj;
    if (j == 0) { g_bp[0] = 0.f; g_bp[129] = INF; }
}

// per-segment slope/intercept: f_d(rel) = slope*rel + inter  (SCALE = 1)
__global__ void build_table_kernel(const float* __restrict__ Wp1,
                                   const float* __restrict__ bp1,
                                   const float* __restrict__ Wp2,
                                   const float* __restrict__ bp2) {
    int seg = blockIdx.x;       // 0..128
    int d   = threadIdx.x;      // 0..255
    float lo = g_bp[seg], hi = g_bp[seg + 1];
    float mid = isinf(hi) ? (lo + 1.0f) : 0.5f * (lo + hi);
    float s = 0.f, c = 0.f;
    for (int j = 0; j < PHC; j++) {
        float a = Wp1[j], b = bp1[j];
        if (a * mid + b > 0.f) {             // neuron active on this segment
            float w = Wp2[d * PHC + j];
            s += a * w;
            c += b * w;
        }
    }
    g_slope[seg * DIMC + d] = s;
    g_inter[seg * DIMC + d] = c + bp2[d];
}

// ---------------- fp32 GEMM:  C[M,Nout] = A[M,K] * B[Nout,K]^T + bias ----------------
// BM=BN=128, BK=16, 256 threads, 8x8 per thread, double-buffered smem
__global__ __launch_bounds__(256, 2)
void sgemm_abt_kernel(const float* __restrict__ A, const float* __restrict__ B,
                      const float* __restrict__ bias, float* __restrict__ C,
                      int M, int Nout, int K) {
    __shared__ float As[2][16][128];
    __shared__ float Bs[2][16][128];
    const int tid = threadIdx.x;
    const int tx  = tid & 15;
    const int ty  = tid >> 4;
    const int rowBase = blockIdx.y * 128;
    const int colBase = blockIdx.x * 128;
    const int ldRow = tid >> 2;          // 0..63
    const int ldCol = (tid & 3) << 2;    // 0,4,8,12

    float acc[8][8];
#pragma unroll
    for (int i = 0; i < 8; i++)
#pragma unroll
        for (int j = 0; j < 8; j++) acc[i][j] = 0.f;

    const float* Aptr = A + (size_t)(rowBase + ldRow) * K + ldCol;
    const float* Bptr = B + (size_t)(colBase + ldRow) * K + ldCol;

    // prologue: load tile 0 into buffer 0
    {
        float4 a0 = *(const float4*)(Aptr);
        float4 a1 = *(const float4*)(Aptr + (size_t)64 * K);
        float4 b0 = *(const float4*)(Bptr);
        float4 b1 = *(const float4*)(Bptr + (size_t)64 * K);
        As[0][ldCol + 0][ldRow]      = a0.x; As[0][ldCol + 1][ldRow]      = a0.y;
        As[0][ldCol + 2][ldRow]      = a0.z; As[0][ldCol + 3][ldRow]      = a0.w;
        As[0][ldCol + 0][ldRow + 64] = a1.x; As[0][ldCol + 1][ldRow + 64] = a1.y;
        As[0][ldCol + 2][ldRow + 64] = a1.z; As[0][ldCol + 3][ldRow + 64] = a1.w;
        Bs[0][ldCol + 0][ldRow]      = b0.x; Bs[0][ldCol + 1][ldRow]      = b0.y;
        Bs[0][ldCol + 2][ldRow]      = b0.z; Bs[0][ldCol + 3][ldRow]      = b0.w;
        Bs[0][ldCol + 0][ldRow + 64] = b1.x; Bs[0][ldCol + 1][ldRow + 64] = b1.y;
        Bs[0][ldCol + 2][ldRow + 64] = b1.z; Bs[0][ldCol + 3][ldRow + 64] = b1.w;
    }
    __syncthreads();

    int buf = 0;
    for (int k0 = 0; k0 < K; k0 += 16) {
        int knext = k0 + 16;
        float4 a0, a1, b0, b1;
        bool have_next = (knext < K);
        if (have_next) {
            a0 = *(const float4*)(Aptr + knext);
            a1 = *(const float4*)(Aptr + (size_t)64 * K + knext);
            b0 = *(const float4*)(Bptr + knext);
            b1 = *(const float4*)(Bptr + (size_t)64 * K + knext);
        }
#pragma unroll
        for (int k = 0; k < 16; k++) {
            float4 ra0 = *(const float4*)&As[buf][k][ty * 8];
            float4 ra1 = *(const float4*)&As[buf][k][ty * 8 + 4];
            float4 rb0 = *(const float4*)&Bs[buf][k][tx * 8];
            float4 rb1 = *(const float4*)&Bs[buf][k][tx * 8 + 4];
            float ra[8] = {ra0.x, ra0.y, ra0.z, ra0.w, ra1.x, ra1.y, ra1.z, ra1.w};
            float rb[8] = {rb0.x, rb0.y, rb0.z, rb0.w, rb1.x, rb1.y, rb1.z, rb1.w};
#pragma unroll
            for (int i = 0; i < 8; i++)
#pragma unroll
                for (int j = 0; j < 8; j++)
                    acc[i][j] = fmaf(ra[i], rb[j], acc[i][j]);
        }
        if (have_next) {
            int nb = buf ^ 1;
            __syncthreads();
            As[nb][ldCol + 0][ldRow]      = a0.x; As[nb][ldCol + 1][ldRow]      = a0.y;
            As[nb][ldCol + 2][ldRow]      = a0.z; As[nb][ldCol + 3][ldRow]      = a0.w;
            As[nb][ldCol + 0][ldRow + 64] = a1.x; As[nb][ldCol + 1][ldRow + 64] = a1.y;
            As[nb][ldCol + 2][ldRow + 64] = a1.z; As[nb][ldCol + 3][ldRow + 64] = a1.w;
            Bs[nb][ldCol + 0][ldRow]      = b0.x; Bs[nb][ldCol + 1][ldRow]      = b0.y;
            Bs[nb][ldCol + 2][ldRow]      = b0.z; Bs[nb][ldCol + 3][ldRow]      = b0.w;
            Bs[nb][ldCol + 0][ldRow + 64] = b1.x; Bs[nb][ldCol + 1][ldRow + 64] = b1.y;
            Bs[nb][ldCol + 2][ldRow + 64] = b1.z; Bs[nb][ldCol + 3][ldRow + 64] = b1.w;
            __syncthreads();
            buf = nb;
        }
    }
#pragma unroll
    for (int i = 0; i < 8; i++) {
        int r = rowBase + ty * 8 + i;
        float* crow = C + (size_t)r * Nout + colBase + tx * 8;
#pragma unroll
        for (int j = 0; j < 8; j++)
            crow[j] = acc[i][j] + bias[colBase + tx * 8 + j];
    }
}

// ---------------- attention: per-(n,d) softmax over 16 neighbors ----------------
__global__ __launch_bounds__(256)
void attn_kernel(const float* __restrict__ pos, const int* __restrict__ aidx,
                 const void* __restrict__ mask, int N) {
    __shared__ int   s_idx[SNB];
    __shared__ float s_rel[SNB];
    __shared__ int   s_seg[SNB];
    __shared__ int   s_msk[SNB];

    const int n   = blockIdx.x;
    const int tid = threadIdx.x;
    const float NEG_INF = __int_as_float(0xff800000);

    if (tid < SNB) {
        int s = tid;
        int j = aidx[n * SNB + s];
        s_idx[s] = j;
        int mode = g_mask_mode;
        int mv;
        if (mode == 0)      mv = ((const int*)mask)[n * SNB + s] != 0;
        else if (mode == 1) mv = ((const unsigned char*)mask)[n * SNB + s] != 0;
        else                mv = ((const float*)mask)[n * SNB + s] != 0.f;
        s_msk[s] = mv;
        float dx = pos[j * 3 + 0] - pos[n * 3 + 0];
        float dy = pos[j * 3 + 1] - pos[n * 3 + 1];
        float dz = pos[j * 3 + 2] - pos[n * 3 + 2];
        float rel = sqrtf(dx * dx + dy * dy + dz * dz);
        s_rel[s] = rel;
        // binary search: last i in [0,128] with g_bp[i] <= rel
        int lo = 0, hi = 129;
        while (hi - lo > 1) {
            int m = (lo + hi) >> 1;
            if (g_bp[m] <= rel) lo = m; else hi = m;
        }
        s_seg[s] = lo;
    }
    __syncthreads();

    const int d = tid;
    const float qd = g_qkv[(size_t)n * QKVC + d];
    float w[SNB], ro[SNB];
    float wmax = NEG_INF;
#pragma unroll
    for (int s = 0; s < SNB; s++) {
        if (s_msk[s]) { w[s] = NEG_INF; ro[s] = 0.f; continue; }
        int j = s_idx[s];
        int seg = s_seg[s];
        float r = fmaf(g_slope[seg * DIMC + d], s_rel[s], g_inter[seg * DIMC + d]);
        ro[s] = r;
        float kv = __ldg(&g_qkv[(size_t)j * QKVC + DIMC + d]);
        float ww = fmaf(kv, qd, r);
        w[s] = ww;
        wmax = fmaxf(wmax, ww);
    }
    float esum = 0.f, acc = 0.f;
#pragma unroll
    for (int s = 0; s < SNB; s++) {
        if (s_msk[s]) continue;
        float e = __expf(w[s] - wmax);
        esum += e;
        float vv = __ldg(&g_qkv[(size_t)s_idx[s] * QKVC + 2 * DIMC + d]);
        acc = fmaf(e, vv + ro[s], acc);
    }
    g_attn[(size_t)n * DIMC + d] = acc / esum;
}

// ---------------- launch ----------------
extern "C" void kernel_launch(void* const* d_in, const int* in_sizes, int n_in,
                              void* d_out, int out_size) {
    const float* x    = (const float*)d_in[0];
    const float* pos  = (const float*)d_in[1];
    const int*   aidx = (const int*)  d_in[2];
    const void*  mask =               d_in[3];
    const float* Wqkv = (const float*)d_in[4];
    const float* bqkv = (const float*)d_in[5];
    const float* Wp1  = (const float*)d_in[6];
    const float* bp1  = (const float*)d_in[7];
    const float* Wp2  = (const float*)d_in[8];
    const float* bp2  = (const float*)d_in[9];
    const float* Wo   = (const float*)d_in[10];
    const float* bo   = (const float*)d_in[11];
    float* out = (float*)d_out;

    int N = in_sizes[0] / DIMC;
    if (N > NMAX) N = NMAX;

    float* qkv_ptr  = nullptr;
    float* attn_ptr = nullptr;
    cudaGetSymbolAddress((void**)&qkv_ptr,  g_qkv);
    cudaGetSymbolAddress((void**)&attn_ptr, g_attn);

    detect_mask_kernel<<<1, 256>>>((const unsigned*)mask, in_sizes[3] / 4);
    build_bp_kernel<<<1, 128>>>(Wp1, bp1);
    build_table_kernel<<<129, 256>>>(Wp1, bp1, Wp2, bp2);

    dim3 g1(QKVC / 128, N / 128);
    sgemm_abt_kernel<<<g1, 256>>>(x, Wqkv, bqkv, qkv_ptr, N, QKVC, DIMC);

    attn_kernel<<<N, 256>>>(pos, aidx, mask, N);

    dim3 g2(DIMC / 128, N / 128);
    sgemm_abt_kernel<<<g2, 256>>>(attn_ptr, Wo, bo, out, N, DIMC, DIMC);
}

// round 8
// speedup vs baseline: 1.2491x; 1.2491x over previous
#include <cuda_runtime.h>
#include <cuda_bf16.h>
#include <math.h>

#define DIMC 256
#define SNB  16
#define PHC  128
#define QKVC 768
#define NMAX 32768

// ---------------- static scratch (no allocation allowed) ----------------
__device__ float g_qkv[(size_t)NMAX * QKVC];   // q|k|v per row, 96 MB
__device__ float g_attn[(size_t)NMAX * DIMC];  // 32 MB
__device__ float g_slope[129 * DIMC];
__device__ float g_inter[129 * DIMC];
__device__ float g_bp[130];
__device__ int   g_mask_mode;                  // 0=int32, 1=uint8, 2=float32
__device__ int   g_flag_other;
__device__ int   g_flag_float;

// ---------------- packed f32x2 helpers ----------------
__device__ __forceinline__ unsigned long long pack_rep2(float a) {
    unsigned long long r;
    asm("mov.b64 %0, {%1, %1};" : "=l"(r) : "f"(a));
    return r;
}
__device__ __forceinline__ void ffma2(unsigned long long& acc,
                                      unsigned long long a,
                                      unsigned long long b) {
    asm("fma.rn.f32x2 %0, %1, %2, %0;" : "+l"(acc) : "l"(a), "l"(b));
}

// ---------------- mask dtype detection (parallel) ----------------
__global__ void reset_flags_kernel() { g_flag_other = 0; g_flag_float = 0; }

__global__ void detect_mask_kernel(const unsigned* __restrict__ m, int nwords) {
    int i = blockIdx.x * blockDim.x + threadIdx.x;
    int flt = 0, other = 0;
    if (i < nwords) {
        unsigned v = m[i];
        if (v == 0x3f800000u) flt = 1;
        else if (v > 1u) other = 1;
    }
    unsigned bf = __ballot_sync(0xffffffffu, flt);
    unsigned bo = __ballot_sync(0xffffffffu, other);
    if ((threadIdx.x & 31) == 0) {
        if (bf) atomicOr(&g_flag_float, 1);
        if (bo) atomicOr(&g_flag_other, 1);
    }
}

__global__ void finalize_mask_kernel() {
    g_mask_mode = g_flag_other ? 1 : (g_flag_float ? 2 : 0);
}

// ---------------- piecewise-linear MLP table ----------------
// breakpoints of relu(Wp1[j]*rel + bp1[j]) as a function of scalar rel >= 0
__global__ void build_bp_kernel(const float* __restrict__ Wp1,
                                const float* __restrict__ bp1) {
    __shared__ float t[PHC];
    int j = threadIdx.x;
    float a = Wp1[j], b = bp1[j];
    float INF = __int_as_float(0x7f800000);
    float tj;
    if (a != 0.f) {
        tj = -b / a;
        if (!(tj > 0.f)) tj = 0.f;          // nonpositive or NaN -> 0 (inactive boundary)
        if (isinf(tj)) tj = INF;
    } else {
        tj = INF;                            // constant neuron: no breakpoint
    }
    t[j] = tj;
    __syncthreads();
    // rank sort (stable with index tiebreak)
    int rank = 0;
    for (int i = 0; i < PHC; i++) {
        float ti = t[i];
        rank += (ti < tj) || (ti == tj && i < j);
    }
    g_bp[rank + 1] = tj;
    if (j == 0) { g_bp[0] = 0.f; g_bp[129] = INF; }
}

// per-segment slope/intercept: f_d(rel) = slope*rel + inter  (SCALE = 1)
__global__ void build_table_kernel(const float* __restrict__ Wp1,
                                   const float* __restrict__ bp1,
                                   const float* __restrict__ Wp2,
                                   const float* __restrict__ bp2) {
    int seg = blockIdx.x;       // 0..128
    int d   = threadIdx.x;      // 0..255
    float lo = g_bp[seg], hi = g_bp[seg + 1];
    float mid = isinf(hi) ? (lo + 1.0f) : 0.5f * (lo + hi);
    float s = 0.f, c = 0.f;
    for (int j = 0; j < PHC; j++) {
        float a = Wp1[j], b = bp1[j];
        if (a * mid + b > 0.f) {             // neuron active on this segment
            float w = Wp2[d * PHC + j];
            s += a * w;
            c += b * w;
        }
    }
    g_slope[seg * DIMC + d] = s;
    g_inter[seg * DIMC + d] = c + bp2[d];
}

// ---------------- fp32 GEMM (packed f32x2 FFMA):  C = A * B^T + bias ----------------
// BM=BN=128, BK=16, 256 threads, 8 rows x 4 packed col-pairs per thread,
// double-buffered smem.
__global__ __launch_bounds__(256, 2)
void sgemm_abt_kernel(const float* __restrict__ A, const float* __restrict__ B,
                      const float* __restrict__ bias, float* __restrict__ C,
                      int M, int Nout, int K) {
    __shared__ float As[2][16][128];
    __shared__ float Bs[2][16][128];
    const int tid = threadIdx.x;
    const int tx  = tid & 15;
    const int ty  = tid >> 4;
    const int rowBase = blockIdx.y * 128;
    const int colBase = blockIdx.x * 128;
    const int ldRow = tid >> 2;          // 0..63
    const int ldCol = (tid & 3) << 2;    // 0,4,8,12

    unsigned long long acc2[8][4];
#pragma unroll
    for (int i = 0; i < 8; i++)
#pragma unroll
        for (int j = 0; j < 4; j++) acc2[i][j] = 0ull;

    const float* Aptr = A + (size_t)(rowBase + ldRow) * K + ldCol;
    const float* Bptr = B + (size_t)(colBase + ldRow) * K + ldCol;

    // prologue: load tile 0 into buffer 0
    {
        float4 a0 = *(const float4*)(Aptr);
        float4 a1 = *(const float4*)(Aptr + (size_t)64 * K);
        float4 b0 = *(const float4*)(Bptr);
        float4 b1 = *(const float4*)(Bptr + (size_t)64 * K);
        As[0][ldCol + 0][ldRow]      = a0.x; As[0][ldCol + 1][ldRow]      = a0.y;
        As[0][ldCol + 2][ldRow]      = a0.z; As[0][ldCol + 3][ldRow]      = a0.w;
        As[0][ldCol + 0][ldRow + 64] = a1.x; As[0][ldCol + 1][ldRow + 64] = a1.y;
        As[0][ldCol + 2][ldRow + 64] = a1.z; As[0][ldCol + 3][ldRow + 64] = a1.w;
        Bs[0][ldCol + 0][ldRow]      = b0.x; Bs[0][ldCol + 1][ldRow]      = b0.y;
        Bs[0][ldCol + 2][ldRow]      = b0.z; Bs[0][ldCol + 3][ldRow]      = b0.w;
        Bs[0][ldCol + 0][ldRow + 64] = b1.x; Bs[0][ldCol + 1][ldRow + 64] = b1.y;
        Bs[0][ldCol + 2][ldRow + 64] = b1.z; Bs[0][ldCol + 3][ldRow + 64] = b1.w;
    }
    __syncthreads();

    int buf = 0;
    for (int k0 = 0; k0 < K; k0 += 16) {
        int knext = k0 + 16;
        float4 a0, a1, b0, b1;
        bool have_next = (knext < K);
        if (have_next) {
            a0 = *(const float4*)(Aptr + knext);
            a1 = *(const float4*)(Aptr + (size_t)64 * K + knext);
            b0 = *(const float4*)(Bptr + knext);
            b1 = *(const float4*)(Bptr + (size_t)64 * K + knext);
        }
#pragma unroll
        for (int k = 0; k < 16; k++) {
            float4 ra0 = *(const float4*)&As[buf][k][ty * 8];
            float4 ra1 = *(const float4*)&As[buf][k][ty * 8 + 4];
            // B pairs: adjacent columns reinterpreted as packed f32x2
            ulonglong2 rbA = *(const ulonglong2*)&Bs[buf][k][tx * 8];
            ulonglong2 rbB = *(const ulonglong2*)&Bs[buf][k][tx * 8 + 4];
            unsigned long long rb2[4] = {rbA.x, rbA.y, rbB.x, rbB.y};
            unsigned long long ra2[8];
            ra2[0] = pack_rep2(ra0.x); ra2[1] = pack_rep2(ra0.y);
            ra2[2] = pack_rep2(ra0.z); ra2[3] = pack_rep2(ra0.w);
            ra2[4] = pack_rep2(ra1.x); ra2[5] = pack_rep2(ra1.y);
            ra2[6] = pack_rep2(ra1.z); ra2[7] = pack_rep2(ra1.w);
#pragma unroll
            for (int i = 0; i < 8; i++)
#pragma unroll
                for (int j = 0; j < 4; j++)
                    ffma2(acc2[i][j], ra2[i], rb2[j]);
        }
        if (have_next) {
            int nb = buf ^ 1;
            __syncthreads();
            As[nb][ldCol + 0][ldRow]      = a0.x; As[nb][ldCol + 1][ldRow]      = a0.y;
            As[nb][ldCol + 2][ldRow]      = a0.z; As[nb][ldCol + 3][ldRow]      = a0.w;
            As[nb][ldCol + 0][ldRow + 64] = a1.x; As[nb][ldCol + 1][ldRow + 64] = a1.y;
            As[nb][ldCol + 2][ldRow + 64] = a1.z; As[nb][ldCol + 3][ldRow + 64] = a1.w;
            Bs[nb][ldCol + 0][ldRow]      = b0.x; Bs[nb][ldCol + 1][ldRow]      = b0.y;
            Bs[nb][ldCol + 2][ldRow]      = b0.z; Bs[nb][ldCol + 3][ldRow]      = b0.w;
            Bs[nb][ldCol + 0][ldRow + 64] = b1.x; Bs[nb][ldCol + 1][ldRow + 64] = b1.y;
            Bs[nb][ldCol + 2][ldRow + 64] = b1.z; Bs[nb][ldCol + 3][ldRow + 64] = b1.w;
            __syncthreads();
            buf = nb;
        }
    }
#pragma unroll
    for (int i = 0; i < 8; i++) {
        int r = rowBase + ty * 8 + i;
        float* crow = C + (size_t)r * Nout + colBase + tx * 8;
#pragma unroll
        for (int j = 0; j < 4; j++) {
            float2 p = *(float2*)&acc2[i][j];
            crow[2 * j + 0] = p.x + bias[colBase + tx * 8 + 2 * j + 0];
            crow[2 * j + 1] = p.y + bias[colBase + tx * 8 + 2 * j + 1];
        }
    }
}

// ---------------- attention: per-(n,d) softmax over 16 neighbors ----------------
__global__ __launch_bounds__(256)
void attn_kernel(const float* __restrict__ pos, const int* __restrict__ aidx,
                 const void* __restrict__ mask, int N) {
    __shared__ int   s_idx[SNB];
    __shared__ float s_rel[SNB];
    __shared__ int   s_seg[SNB];
    __shared__ int   s_msk[SNB];

    const int n   = blockIdx.x;
    const int tid = threadIdx.x;
    const float NEG_INF = __int_as_float(0xff800000);

    if (tid < SNB) {
        int s = tid;
        int j = aidx[n * SNB + s];
        s_idx[s] = j;
        int mode = g_mask_mode;
        int mv;
        if (mode == 0)      mv = ((const int*)mask)[n * SNB + s] != 0;
        else if (mode == 1) mv = ((const unsigned char*)mask)[n * SNB + s] != 0;
        else                mv = ((const float*)mask)[n * SNB + s] != 0.f;
        s_msk[s] = mv;
        float dx = pos[j * 3 + 0] - pos[n * 3 + 0];
        float dy = pos[j * 3 + 1] - pos[n * 3 + 1];
        float dz = pos[j * 3 + 2] - pos[n * 3 + 2];
        float rel = sqrtf(dx * dx + dy * dy + dz * dz);
        s_rel[s] = rel;
        // binary search: last i in [0,128] with g_bp[i] <= rel
        int lo = 0, hi = 129;
        while (hi - lo > 1) {
            int m = (lo + hi) >> 1;
            if (g_bp[m] <= rel) lo = m; else hi = m;
        }
        s_seg[s] = lo;
    }
    __syncthreads();

    const int d = tid;
    const float qd = g_qkv[(size_t)n * QKVC + d];
    float w[SNB], ro[SNB];
    float wmax = NEG_INF;
#pragma unroll
    for (int s = 0; s < SNB; s++) {
        if (s_msk[s]) { w[s] = NEG_INF; ro[s] = 0.f; continue; }
        int j = s_idx[s];
        int seg = s_seg[s];
        float r = fmaf(g_slope[seg * DIMC + d], s_rel[s], g_inter[seg * DIMC + d]);
        ro[s] = r;
        float kv = __ldg(&g_qkv[(size_t)j * QKVC + DIMC + d]);
        float ww = fmaf(kv, qd, r);
        w[s] = ww;
        wmax = fmaxf(wmax, ww);
    }
    float esum = 0.f, acc = 0.f;
#pragma unroll
    for (int s = 0; s < SNB; s++) {
        if (s_msk[s]) continue;
        float e = __expf(w[s] - wmax);
        esum += e;
        float vv = __ldg(&g_qkv[(size_t)s_idx[s] * QKVC + 2 * DIMC + d]);
        acc = fmaf(e, vv + ro[s], acc);
    }
    g_attn[(size_t)n * DIMC + d] = acc / esum;
}

// ---------------- launch ----------------
extern "C" void kernel_launch(void* const* d_in, const int* in_sizes, int n_in,
                              void* d_out, int out_size) {
    const float* x    = (const float*)d_in[0];
    const float* pos  = (const float*)d_in[1];
    const int*   aidx = (const int*)  d_in[2];
    const void*  mask =               d_in[3];
    const float* Wqkv = (const float*)d_in[4];
    const float* bqkv = (const float*)d_in[5];
    const float* Wp1  = (const float*)d_in[6];
    const float* bp1  = (const float*)d_in[7];
    const float* Wp2  = (const float*)d_in[8];
    const float* bp2  = (const float*)d_in[9];
    const float* Wo   = (const float*)d_in[10];
    const float* bo   = (const float*)d_in[11];
    float* out = (float*)d_out;

    int N = in_sizes[0] / DIMC;
    if (N > NMAX) N = NMAX;

    float* qkv_ptr  = nullptr;
    float* attn_ptr = nullptr;
    cudaGetSymbolAddress((void**)&qkv_ptr,  g_qkv);
    cudaGetSymbolAddress((void**)&attn_ptr, g_attn);

    int nwords = in_sizes[3] / 4;   // safe lower bound on 4-byte words in mask buffer
    reset_flags_kernel<<<1, 1>>>();
    detect_mask_kernel<<<(nwords + 255) / 256, 256>>>((const unsigned*)mask, nwords);
    finalize_mask_kernel<<<1, 1>>>();

    build_bp_kernel<<<1, 128>>>(Wp1, bp1);
    build_table_kernel<<<129, 256>>>(Wp1, bp1, Wp2, bp2);

    dim3 g1(QKVC / 128, N / 128);
    sgemm_abt_kernel<<<g1, 256>>>(x, Wqkv, bqkv, qkv_ptr, N, QKVC, DIMC);

    attn_kernel<<<N, 256>>>(pos, aidx, mask, N);

    dim3 g2(DIMC / 128, N / 128);
    sgemm_abt_kernel<<<g2, 256>>>(attn_ptr, Wo, bo, out, N, DIMC, DIMC);
}